// round 11
// baseline (speedup 1.0000x reference)
#include <cuda_runtime.h>

// ContourChamferLoss on GB300 (sm_103a) — round 10
// Tile-centric exact NN: block per 2x2 cell core, 4x4 region candidates in smem,
// both directions per block. Results keyed by original index -> bit-deterministic.

#define NP_TOT 64000
#define NR_TOT 80000
#define NP     8000
#define NR     10000
#define NTOT   (NP + NR)

// exact f32 replication of jnp.linspace(0, n-1, n//8) index math
#define DELTA_P ((float)(NP_TOT - 1) / (float)(NP - 1))
#define DELTA_R ((float)(NR_TOT - 1) / (float)(NR - 1))

#define GK    32
#define NCELL (GK * GK)
#define CS    (1.0f / (float)GK)
#define CAP   128
#define SBCAP 1024                 // smem candidate capacity per side

#define STPB     256
#define S_BLOCKS ((NTOT + STPB - 1) / STPB)    // 71

#define TPB   128
#define NBLK  256                  // 16x16 groups of 2x2 cells

#define FULLM 0xFFFFFFFFu

// ---- device scratch (static zero-init; no allocation) ----
// Counters zeroed by last search block each run (replay-stable). g_v fully
// overwritten every run. Bucket slot order may vary run-to-run, but results
// are keyed by original index and min is order-independent -> bit-deterministic.
__device__ int    g_cntP[NCELL];
__device__ int    g_cntR[NCELL];
__device__ float2 g_ptsP[NCELL * CAP];
__device__ float2 g_ptsR[NCELL * CAP];
__device__ int    g_kP[NCELL * CAP];     // original global index (0..NP-1)
__device__ int    g_kR[NCELL * CAP];     // NP + (0..NR-1)
__device__ float  g_v[NTOT];             // per-query sqrt(dmin)
__device__ unsigned int g_ctr;

__device__ __forceinline__ int clamp_cell(int c) {
    return c < 0 ? 0 : (c > GK - 1 ? GK - 1 : c);
}

// ---------------- scatter: subsample gather + bucket append ----------------
__global__ __launch_bounds__(STPB) void scatter_kernel(const float* __restrict__ pc,
                                                       const float* __restrict__ ref) {
    int k = blockIdx.x * STPB + threadIdx.x;
    if (k < NP) {
        int i = (int)((float)k * DELTA_P);
        float2 p = *reinterpret_cast<const float2*>(pc + 2 * i);
        int c = clamp_cell((int)(p.y * (float)GK)) * GK + clamp_cell((int)(p.x * (float)GK));
        int s = atomicAdd(&g_cntP[c], 1);
        if (s < CAP) { g_ptsP[c * CAP + s] = p; g_kP[c * CAP + s] = k; }
    } else if (k < NTOT) {
        int j = k - NP;
        int i = (int)((float)j * DELTA_R);
        float2 p = *reinterpret_cast<const float2*>(ref + 2 * i);
        int c = clamp_cell((int)(p.y * (float)GK)) * GK + clamp_cell((int)(p.x * (float)GK));
        int s = atomicAdd(&g_cntR[c], 1);
        if (s < CAP) { g_ptsR[c * CAP + s] = p; g_kR[c * CAP + s] = k; }
    }
}

// scan one global cell
__device__ __forceinline__ void scan_cell_g(const float2* __restrict__ pts,
                                            const int* __restrict__ cnt,
                                            int c, float px, float py, float& dmin) {
    int m = cnt[c];
    m = m < CAP ? m : CAP;
    const float2* q = pts + c * CAP;
    for (int t = 0; t < m; t++) {
        float2 pp = q[t];
        float ddx = px - pp.x, ddy = py - pp.y;
        dmin = fminf(dmin, fmaf(ddx, ddx, ddy * ddy));
    }
}

// ---------------- search: tile-centric, both directions per block ----------------
__global__ __launch_bounds__(TPB) void search_kernel(float* __restrict__ out) {
    __shared__ float2 sbuf[2][SBCAP];          // [0]=P candidates, [1]=R candidates
    __shared__ int    skid[2][SBCAP];
    __shared__ int sCellT[2][16], sOffT[2][16], sCntT[2][16];
    __shared__ int sTot[2];
    __shared__ int sCoreOff[2][4], sCoreCnt[2][4];

    int tid = threadIdx.x, lane = tid & 31, wid = tid >> 5;
    int b = blockIdx.x;
    int gx0 = (b & 15) * 2, gy0 = (b >> 4) * 2;
    int x0 = gx0 - 1 < 0 ? 0 : gx0 - 1;
    int x1 = gx0 + 2 > GK - 1 ? GK - 1 : gx0 + 2;
    int y0 = gy0 - 1 < 0 ? 0 : gy0 - 1;
    int y1 = gy0 + 2 > GK - 1 ? GK - 1 : gy0 + 2;
    int nx = x1 - x0 + 1, ny = y1 - y0 + 1, nc = nx * ny;   // 9..16

    // ---- warps 0,1: build region tables (counts, prefix offsets) ----
    if (wid < 2) {
        int side = wid;                         // 0=P buckets, 1=R buckets
        const int* cnt = side ? g_cntR : g_cntP;
        int m = 0, cellid = 0;
        if (lane < nc) {
            int ix = lane % nx, iy = lane / nx;
            cellid = (y0 + iy) * GK + (x0 + ix);
            int mm = cnt[cellid];
            m = mm < CAP ? mm : CAP;
        }
        int incl = m;
        #pragma unroll
        for (int o = 1; o < 32; o <<= 1) {
            int t = __shfl_up_sync(FULLM, incl, o);
            if (lane >= o) incl += t;
        }
        int off = incl - m;
        if (lane < nc) { sCellT[side][lane] = cellid; sOffT[side][lane] = off; sCntT[side][lane] = m; }
        if (lane == 31) sTot[side] = incl;
        // core cell (dx,dy) -> region linear index; lanes 0..3 publish
        int dx = lane & 1, dy = (lane >> 1) & 1;
        int ridx = (gy0 + dy - y0) * nx + (gx0 + dx - x0);
        int coff = __shfl_sync(FULLM, off, ridx);
        int ccnt = __shfl_sync(FULLM, m, ridx);
        if (lane < 4) { sCoreOff[side][lane] = coff; sCoreCnt[side][lane] = ccnt; }
    }
    __syncthreads();

    int totP = sTot[0], totR = sTot[1];
    bool ovf = (totP > SBCAP) || (totR > SBCAP);

    // ---- cooperative copy of region candidates into smem ----
    if (!ovf) {
        for (int j = wid; j < 2 * nc; j += TPB / 32) {
            int side = j < nc ? 0 : 1;
            int idx  = j < nc ? j : j - nc;
            int cell = sCellT[side][idx];
            int off  = sOffT[side][idx];
            int m    = sCntT[side][idx];
            const float2* src = side ? g_ptsR : g_ptsP;
            const int*    srk = side ? g_kR  : g_kP;
            for (int s = lane; s < m; s += 32) {
                sbuf[side][off + s] = src[cell * CAP + s];
                skid[side][off + s] = srk[cell * CAP + s];
            }
        }
    }
    __syncthreads();

    int nQP = sCoreCnt[0][0] + sCoreCnt[0][1] + sCoreCnt[0][2] + sCoreCnt[0][3];
    int nQR = sCoreCnt[1][0] + sCoreCnt[1][1] + sCoreCnt[1][2] + sCoreCnt[1][3];
    int nQ = nQP + nQR;

    // ---- queries: core points of both sides scan opposite-side smem list ----
    for (int qi = tid; qi < nQ; qi += TPB) {
        int qs = qi < nQP ? 0 : 1;               // query's own side
        int rem = qs ? qi - nQP : qi;
        int cc = 0;
        while (cc < 3 && rem >= sCoreCnt[qs][cc]) { rem -= sCoreCnt[qs][cc]; cc++; }

        float2 qp; int gk;
        if (!ovf) {
            int pos = sCoreOff[qs][cc] + rem;
            qp = sbuf[qs][pos];
            gk = skid[qs][pos];
        } else {
            int cell = (gy0 + (cc >> 1)) * GK + (gx0 + (cc & 1));
            qp = (qs ? g_ptsR : g_ptsP)[cell * CAP + rem];
            gk = (qs ? g_kR  : g_kP )[cell * CAP + rem];
        }
        float px = qp.x, py = qp.y;
        float dmin = 1e30f;

        int os = 1 - qs;                         // opposite side (candidates)
        if (!ovf) {
            int tot = os ? totR : totP;
            const float2* cb = sbuf[os];
            #pragma unroll 4
            for (int s = 0; s < tot; s++) {
                float2 pp = cb[s];
                float ddx = px - pp.x, ddy = py - pp.y;
                dmin = fminf(dmin, fmaf(ddx, ddx, ddy * ddy));
            }
        }

        // global fallback paths (rare / overflow): exact expanding-ring search
        const float2* gpts = os ? g_ptsR : g_ptsP;
        const int*    gcnt = os ? g_cntR : g_cntP;
        int cx = clamp_cell((int)(px * (float)GK));
        int cy = clamp_cell((int)(py * (float)GK));
        if (ovf) {
            for (int yy = clamp_cell(cy - 1); yy <= clamp_cell(cy + 1); yy++)
                for (int xx = clamp_cell(cx - 1); xx <= clamp_cell(cx + 1); xx++)
                    scan_cell_g(gpts, gcnt, yy * GK + xx, px, py, dmin);
        }
        int r = 1;
        float cov = CS;
        while (dmin > cov * cov && r < GK - 1) {
            r++;
            cov = (float)r * CS;
            for (int dy = -r; dy <= r; dy++) {
                int yy = cy + dy;
                if (yy < 0 || yy >= GK) continue;
                int step = (dy == -r || dy == r) ? 1 : 2 * r;
                for (int xx = cx - r; xx <= cx + r; xx += step) {
                    if (xx < 0 || xx >= GK) continue;
                    scan_cell_g(gpts, gcnt, yy * GK + xx, px, py, dmin);
                }
            }
        }

        g_v[gk] = sqrtf(dmin);
    }

    // ---- ticket; last-arriving block: fixed-order final sum + state reset ----
    __threadfence();
    __syncthreads();
    __shared__ int lastf;
    if (tid == 0) {
        unsigned int done = atomicAdd(&g_ctr, 1u);
        lastf = (done == NBLK - 1) ? 1 : 0;
    }
    __syncthreads();

    if (lastf) {
        if (tid == 0) __threadfence();
        __syncthreads();

        float acc = 0.f;
        #pragma unroll 4
        for (int k = tid; k < NTOT; k += TPB) {
            float d = __ldcg(&g_v[k]);
            acc += d * (k < NP ? (0.5f / (float)NP) : (0.5f / (float)NR));
        }
        #pragma unroll
        for (int o = 16; o > 0; o >>= 1)
            acc += __shfl_xor_sync(FULLM, acc, o);

        __shared__ float sw2[TPB / 32];
        if (lane == 0) sw2[wid] = acc;
        __syncthreads();
        if (tid == 0) {
            float t = 0.f;
            #pragma unroll
            for (int w = 0; w < TPB / 32; w++) t += sw2[w];
            out[0] = t;
            g_ctr = 0;
        }
        for (int c = tid; c < NCELL; c += TPB) {
            g_cntP[c] = 0;
            g_cntR[c] = 0;
        }
    }
}

extern "C" void kernel_launch(void* const* d_in, const int* in_sizes, int n_in,
                              void* d_out, int out_size) {
    const float* pc  = (const float*)d_in[0];   // img_render_points (64000 x 2)
    const float* ref = (const float*)d_in[1];   // ref point cloud   (80000 x 2)

    scatter_kernel<<<S_BLOCKS, STPB>>>(pc, ref);
    search_kernel<<<NBLK, TPB>>>((float*)d_out);
}

// round 12
// speedup vs baseline: 1.2587x; 1.2587x over previous
#include <cuda_runtime.h>

// ContourChamferLoss on GB300 (sm_103a) — round 12
// ONE fused kernel: scatter -> software grid barrier -> paired-thread exact NN
// search -> deterministic hierarchical reduction. 32x32 grid, expanding-ring
// fallback for exactness.

#define NP_TOT 64000
#define NR_TOT 80000
#define NP     8000
#define NR     10000
#define NTOT   (NP + NR)

// exact f32 replication of jnp.linspace(0, n-1, n//8) index math
#define DELTA_P ((float)(NP_TOT - 1) / (float)(NP - 1))
#define DELTA_R ((float)(NR_TOT - 1) / (float)(NR - 1))

#define GK    32
#define NCELL (GK * GK)
#define CS    (1.0f / (float)GK)
#define CAP   128

#define TPB   128
#define QPB   (TPB / 2)                  // 64 queries per block (2 threads/query)
#define NBLK  ((NTOT + QPB - 1) / QPB)   // 282 blocks (all co-resident)

#define FULLM 0xFFFFFFFFu

// ---- device scratch (static zero-init; no allocation) ----
// All counters are reset by the last block each run -> graph replays start
// clean. Bucket slot order may vary run-to-run, but min over a set is
// order-independent and partial sums are keyed by query index -> bit-stable.
__device__ int    g_cntP[NCELL];
__device__ int    g_cntR[NCELL];
__device__ float2 g_ptsP[NCELL * CAP];
__device__ float2 g_ptsR[NCELL * CAP];
__device__ float  g_part[NBLK];
__device__ unsigned int g_sync1;         // scatter-done barrier
__device__ unsigned int g_sync2;         // search-done ticket

__device__ __forceinline__ int clamp_cell(int c) {
    return c < 0 ? 0 : (c > GK - 1 ? GK - 1 : c);
}

__device__ __forceinline__ void scan_cell_g(const float2* __restrict__ pts,
                                            const int* __restrict__ cnt,
                                            int c, float px, float py, float& dmin) {
    int m = cnt[c];
    m = m < CAP ? m : CAP;
    const float2* q = pts + c * CAP;
    for (int t = 0; t < m; t++) {
        float2 pp = q[t];
        float ddx = px - pp.x, ddy = py - pp.y;
        dmin = fminf(dmin, fmaf(ddx, ddx, ddy * ddy));
    }
}

__global__ __launch_bounds__(TPB) void chamfer_fused(const float* __restrict__ pc,
                                                     const float* __restrict__ ref,
                                                     float* __restrict__ out) {
    int tid = threadIdx.x;
    int b   = blockIdx.x;

    // ================= phase 1: scatter (1 point per thread) =================
    int g = b * TPB + tid;
    if (g < NP) {
        int i = (int)((float)g * DELTA_P);
        float2 p = *reinterpret_cast<const float2*>(pc + 2 * i);
        int c = clamp_cell((int)(p.y * (float)GK)) * GK + clamp_cell((int)(p.x * (float)GK));
        int s = atomicAdd(&g_cntP[c], 1);
        if (s < CAP) g_ptsP[c * CAP + s] = p;
    } else if (g < NTOT) {
        int j = g - NP;
        int i = (int)((float)j * DELTA_R);
        float2 p = *reinterpret_cast<const float2*>(ref + 2 * i);
        int c = clamp_cell((int)(p.y * (float)GK)) * GK + clamp_cell((int)(p.x * (float)GK));
        int s = atomicAdd(&g_cntR[c], 1);
        if (s < CAP) g_ptsR[c * CAP + s] = p;
    }

    // ================= software grid barrier (all blocks co-resident) ========
    __syncthreads();
    if (tid == 0) {
        __threadfence();                               // release scatter writes
        atomicAdd(&g_sync1, 1u);
        unsigned int v;
        do {
            asm volatile("ld.acquire.gpu.u32 %0, [%1];"
                         : "=r"(v) : "l"(&g_sync1) : "memory");
            if (v < NBLK) __nanosleep(64);
        } while (v < NBLK);
    }
    __syncthreads();                                   // whole block sees done

    // ================= phase 2: search (2 threads per query) =================
    int q   = b * QPB + (tid >> 1);
    int par = tid & 1;
    float v = 0.f;

    if (q < NTOT) {
        const float2* pts;
        const int* cnt;
        const float* own;
        float delta, scale;
        int k;
        if (q < NP) {
            pts = g_ptsR; cnt = g_cntR; own = pc;
            delta = DELTA_P; scale = 0.5f / (float)NP; k = q;
        } else {
            pts = g_ptsP; cnt = g_cntP; own = ref;
            delta = DELTA_R; scale = 0.5f / (float)NR; k = q - NP;
        }

        int i = (int)((float)k * delta);
        float2 p = *reinterpret_cast<const float2*>(own + 2 * i);
        float px = p.x, py = p.y;
        int cx = clamp_cell((int)(px * (float)GK));
        int cy = clamp_cell((int)(py * (float)GK));

        // my half of the 3x3 neighborhood: cells par, par+2, ... (<=5 cells)
        int cells[5], ms[5], ncl = 0;
        #pragma unroll
        for (int c = 0; c < 9; c++) {
            if ((c & 1) != par) continue;
            int yy = cy + c / 3 - 1;
            int xx = cx + c % 3 - 1;
            if (yy >= 0 && yy < GK && xx >= 0 && xx < GK)
                cells[ncl++] = yy * GK + xx;
        }
        // prefetch all counts (independent loads, MLP ~5)
        #pragma unroll
        for (int t = 0; t < 5; t++) {
            int m = (t < ncl) ? cnt[cells[t]] : 0;
            ms[t] = m < CAP ? m : CAP;
        }

        float dmin = 1e30f;
        #pragma unroll
        for (int t = 0; t < 5; t++) {
            int base = cells[t] * CAP;
            int m = ms[t];
            for (int s = 0; s < m; s++) {
                float2 pp = pts[base + s];
                float ddx = px - pp.x, ddy = py - pp.y;
                dmin = fminf(dmin, fmaf(ddx, ddx, ddy * ddy));
            }
        }

        // combine the pair (xor-1 partner in same warp)
        dmin = fminf(dmin, __shfl_xor_sync(FULLM, dmin, 1));

        if (par == 0) {
            // expanding-ring fallback (rare): after radius-r square, coverage r*CS
            int r = 1;
            float cov = CS;
            while (dmin > cov * cov && r < GK - 1) {
                r++;
                cov = (float)r * CS;
                for (int dy = -r; dy <= r; dy++) {
                    int yy = cy + dy;
                    if (yy < 0 || yy >= GK) continue;
                    int step = (dy == -r || dy == r) ? 1 : 2 * r;
                    for (int xx = cx - r; xx <= cx + r; xx += step) {
                        if (xx < 0 || xx >= GK) continue;
                        scan_cell_g(pts, cnt, yy * GK + xx, px, py, dmin);
                    }
                }
            }
            v = sqrtf(dmin) * scale;
        }
    }

    // ================= phase 3: deterministic reduction =================
    // warp sum (fixed shuffle topology) -> smem (fixed slots) -> fixed-order
    #pragma unroll
    for (int o = 16; o > 0; o >>= 1)
        v += __shfl_xor_sync(FULLM, v, o);

    __shared__ float sw[TPB / 32];
    int lane = tid & 31, wid = tid >> 5;
    if (lane == 0) sw[wid] = v;
    __syncthreads();

    __shared__ int lastf;
    if (tid == 0) {
        float s = 0.f;
        #pragma unroll
        for (int w = 0; w < TPB / 32; w++) s += sw[w];
        g_part[b] = s;
        __threadfence();
        unsigned int done = atomicAdd(&g_sync2, 1u);
        lastf = (done == NBLK - 1) ? 1 : 0;
    }
    __syncthreads();

    if (lastf) {
        if (tid == 0) __threadfence();
        __syncthreads();

        // fixed per-thread strided order over 282 partials -> deterministic
        float acc = 0.f;
        for (int t = tid; t < NBLK; t += TPB)
            acc += g_part[t];

        #pragma unroll
        for (int o = 16; o > 0; o >>= 1)
            acc += __shfl_xor_sync(FULLM, acc, o);
        if (lane == 0) sw[wid] = acc;
        __syncthreads();

        if (tid == 0) {
            float t = 0.f;
            #pragma unroll
            for (int w = 0; w < TPB / 32; w++) t += sw[w];
            out[0] = t;
            g_sync1 = 0;
            g_sync2 = 0;
        }
        // zero bucket counters for next graph replay (all readers finished)
        for (int c = tid; c < NCELL; c += TPB) {
            g_cntP[c] = 0;
            g_cntR[c] = 0;
        }
    }
}

extern "C" void kernel_launch(void* const* d_in, const int* in_sizes, int n_in,
                              void* d_out, int out_size) {
    const float* pc  = (const float*)d_in[0];   // img_render_points (64000 x 2)
    const float* ref = (const float*)d_in[1];   // ref point cloud   (80000 x 2)

    chamfer_fused<<<NBLK, TPB>>>(pc, ref, (float*)d_out);
}

// round 13
// speedup vs baseline: 1.5551x; 1.2355x over previous
#include <cuda_runtime.h>

// ContourChamferLoss on GB300 (sm_103a) — round 13
// ONE fused kernel: scatter -> software grid barrier -> 4-threads-per-query
// exact NN (float4 candidate loads) -> deterministic reduction.

#define NP_TOT 64000
#define NR_TOT 80000
#define NP     8000
#define NR     10000
#define NTOT   (NP + NR)

// exact f32 replication of jnp.linspace(0, n-1, n//8) index math
#define DELTA_P ((float)(NP_TOT - 1) / (float)(NP - 1))
#define DELTA_R ((float)(NR_TOT - 1) / (float)(NR - 1))

#define GK    32
#define NCELL (GK * GK)
#define CS    (1.0f / (float)GK)
#define CAP   128

#define TPB   128
#define QPB   (TPB / 4)                  // 32 queries per block (4 threads/query)
#define NBLK  ((NTOT + QPB - 1) / QPB)   // 563 blocks (all co-resident, <=4/SM)

#define FULLM 0xFFFFFFFFu

// ---- device scratch (static zero-init; no allocation) ----
// Counters reset by last block each run -> graph replays start clean.
// Bucket slot order may vary, but min is order-independent and partial sums
// are keyed by query index -> bit-stable output.
__device__ int    g_cntP[NCELL];
__device__ int    g_cntR[NCELL];
__device__ float2 g_ptsP[NCELL * CAP];
__device__ float2 g_ptsR[NCELL * CAP];
__device__ float  g_part[NBLK];
__device__ unsigned int g_sync1;         // scatter-done barrier
__device__ unsigned int g_sync2;         // search-done ticket

__device__ __forceinline__ int clamp_cell(int c) {
    return c < 0 ? 0 : (c > GK - 1 ? GK - 1 : c);
}

__device__ __forceinline__ void scan_cell_g(const float2* __restrict__ pts,
                                            const int* __restrict__ cnt,
                                            int c, float px, float py, float& dmin) {
    int m = cnt[c];
    m = m < CAP ? m : CAP;
    const float2* q = pts + c * CAP;
    for (int t = 0; t < m; t++) {
        float2 pp = q[t];
        float ddx = px - pp.x, ddy = py - pp.y;
        dmin = fminf(dmin, fmaf(ddx, ddx, ddy * ddy));
    }
}

__global__ __launch_bounds__(TPB) void chamfer_fused(const float* __restrict__ pc,
                                                     const float* __restrict__ ref,
                                                     float* __restrict__ out) {
    int tid = threadIdx.x;
    int b   = blockIdx.x;

    // ================= phase 1: scatter (first 141 blocks carry points) ======
    int g = b * TPB + tid;
    if (g < NP) {
        int i = (int)((float)g * DELTA_P);
        float2 p = *reinterpret_cast<const float2*>(pc + 2 * i);
        int c = clamp_cell((int)(p.y * (float)GK)) * GK + clamp_cell((int)(p.x * (float)GK));
        int s = atomicAdd(&g_cntP[c], 1);
        if (s < CAP) g_ptsP[c * CAP + s] = p;
    } else if (g < NTOT) {
        int j = g - NP;
        int i = (int)((float)j * DELTA_R);
        float2 p = *reinterpret_cast<const float2*>(ref + 2 * i);
        int c = clamp_cell((int)(p.y * (float)GK)) * GK + clamp_cell((int)(p.x * (float)GK));
        int s = atomicAdd(&g_cntR[c], 1);
        if (s < CAP) g_ptsR[c * CAP + s] = p;
    }

    // ================= software grid barrier (all blocks co-resident) ========
    __syncthreads();
    if (tid == 0) {
        __threadfence();                               // release scatter writes
        atomicAdd(&g_sync1, 1u);
        unsigned int v;
        do {
            asm volatile("ld.acquire.gpu.u32 %0, [%1];"
                         : "=r"(v) : "l"(&g_sync1) : "memory");
            if (v < NBLK) __nanosleep(64);
        } while (v < NBLK);
    }
    __syncthreads();

    // ================= phase 2: search (4 threads per query) =================
    int q   = (b * TPB + tid) >> 2;
    int par = tid & 3;
    float v = 0.f;

    if (q < NTOT) {
        const float2* pts;
        const int* cnt;
        const float* own;
        float delta, scale;
        int k;
        if (q < NP) {
            pts = g_ptsR; cnt = g_cntR; own = pc;
            delta = DELTA_P; scale = 0.5f / (float)NP; k = q;
        } else {
            pts = g_ptsP; cnt = g_cntP; own = ref;
            delta = DELTA_R; scale = 0.5f / (float)NR; k = q - NP;
        }

        int i = (int)((float)k * delta);
        float2 p = *reinterpret_cast<const float2*>(own + 2 * i);
        float px = p.x, py = p.y;
        int cx = clamp_cell((int)(px * (float)GK));
        int cy = clamp_cell((int)(py * (float)GK));

        // my share of the 3x3 neighborhood: cells par, par+4, par+8 (<=3)
        int cells[3], ms[3], ncl = 0;
        #pragma unroll
        for (int c = par; c < 9; c += 4) {
            int yy = cy + c / 3 - 1;
            int xx = cx + c % 3 - 1;
            if (yy >= 0 && yy < GK && xx >= 0 && xx < GK)
                cells[ncl++] = yy * GK + xx;
        }
        // prefetch counts (independent loads)
        #pragma unroll
        for (int t = 0; t < 3; t++) {
            int m = (t < ncl) ? cnt[cells[t]] : 0;
            ms[t] = m < CAP ? m : CAP;
        }

        float dmin = 1e30f;
        #pragma unroll
        for (int t = 0; t < 3; t++) {
            const float2* basep = pts + cells[t] * CAP;   // 16B-aligned (CAP even)
            int m = ms[t];
            int s = 0;
            for (; s + 2 <= m; s += 2) {                  // 2 points per LDG.128
                float4 pq = *reinterpret_cast<const float4*>(basep + s);
                float dx0 = px - pq.x, dy0 = py - pq.y;
                float dx1 = px - pq.z, dy1 = py - pq.w;
                dmin = fminf(dmin, fmaf(dx0, dx0, dy0 * dy0));
                dmin = fminf(dmin, fmaf(dx1, dx1, dy1 * dy1));
            }
            if (s < m) {
                float2 pp = basep[s];
                float ddx = px - pp.x, ddy = py - pp.y;
                dmin = fminf(dmin, fmaf(ddx, ddx, ddy * ddy));
            }
        }

        // combine the 4 partners (contiguous lanes of one warp)
        dmin = fminf(dmin, __shfl_xor_sync(FULLM, dmin, 1));
        dmin = fminf(dmin, __shfl_xor_sync(FULLM, dmin, 2));

        if (par == 0) {
            // expanding-ring fallback (rare): after radius-r square, coverage r*CS
            int r = 1;
            float cov = CS;
            while (dmin > cov * cov && r < GK - 1) {
                r++;
                cov = (float)r * CS;
                for (int dy = -r; dy <= r; dy++) {
                    int yy = cy + dy;
                    if (yy < 0 || yy >= GK) continue;
                    int step = (dy == -r || dy == r) ? 1 : 2 * r;
                    for (int xx = cx - r; xx <= cx + r; xx += step) {
                        if (xx < 0 || xx >= GK) continue;
                        scan_cell_g(pts, cnt, yy * GK + xx, px, py, dmin);
                    }
                }
            }
            v = sqrtf(dmin) * scale;
        }
    }

    // ================= phase 3: deterministic reduction ======================
    #pragma unroll
    for (int o = 16; o > 0; o >>= 1)
        v += __shfl_xor_sync(FULLM, v, o);

    __shared__ float sw[TPB / 32];
    int lane = tid & 31, wid = tid >> 5;
    if (lane == 0) sw[wid] = v;
    __syncthreads();

    __shared__ int lastf;
    if (tid == 0) {
        float s = 0.f;
        #pragma unroll
        for (int w = 0; w < TPB / 32; w++) s += sw[w];
        g_part[b] = s;
        __threadfence();
        unsigned int done = atomicAdd(&g_sync2, 1u);
        lastf = (done == NBLK - 1) ? 1 : 0;
    }
    __syncthreads();

    if (lastf) {
        if (tid == 0) __threadfence();
        __syncthreads();

        // fixed per-thread strided order over partials -> deterministic
        float acc = 0.f;
        for (int t = tid; t < NBLK; t += TPB)
            acc += g_part[t];

        #pragma unroll
        for (int o = 16; o > 0; o >>= 1)
            acc += __shfl_xor_sync(FULLM, acc, o);
        if (lane == 0) sw[wid] = acc;
        __syncthreads();

        if (tid == 0) {
            float t = 0.f;
            #pragma unroll
            for (int w = 0; w < TPB / 32; w++) t += sw[w];
            out[0] = t;
            g_sync1 = 0;
            g_sync2 = 0;
        }
        // zero bucket counters for next graph replay (all readers finished)
        for (int c = tid; c < NCELL; c += TPB) {
            g_cntP[c] = 0;
            g_cntR[c] = 0;
        }
    }
}

extern "C" void kernel_launch(void* const* d_in, const int* in_sizes, int n_in,
                              void* d_out, int out_size) {
    const float* pc  = (const float*)d_in[0];   // img_render_points (64000 x 2)
    const float* ref = (const float*)d_in[1];   // ref point cloud   (80000 x 2)

    chamfer_fused<<<NBLK, TPB>>>(pc, ref, (float*)d_out);
}